// round 16
// baseline (speedup 1.0000x reference)
#include <cuda_runtime.h>
#include <cuda_fp16.h>
#include <cstdint>

#define N_ROWS   16384
#define DIN      128
#define DOUT     64
#define KDIM     16384
#define MIN_NORM 1e-15f
#define ART_CLAMP (1.0f - 1e-7f)
#define MAXNORM  (1.0f - 4e-3f)

#define MTILE   64
#define TK      64                  // k per chunk
#define NCH     (KDIM / TK)         // 256 chunks
#define APITCH  272                 // A smem row pitch (256B data + 16B pad)
#define ATILE   (MTILE * APITCH)    // 17408
#define BPITCH  144                 // B smem row pitch (128B data + 16B pad)
#define BTILE   (64 * BPITCH)       // 9216
#define STAGE   (ATILE + BTILE)     // 26624
#define BSTAGES 3
#define SMEM_BYTES (BSTAGES * STAGE)   // 79872  -> 2 CTAs/SM

#define A_SCALE 16384.0f            // 2^14 exact; A in [0, 2^-14) -> [0,1)

// Tangent matrix, single fp16, K-major [DOUT][KDIM]
__device__ __half g_Bf[DOUT * KDIM];

// ---------------------------------------------------------------------------
// helpers
// ---------------------------------------------------------------------------
__device__ __forceinline__ uint32_t smem_u32(const void* p) {
    uint32_t a;
    asm("{ .reg .u64 t; cvta.to.shared.u64 t, %1; cvt.u32.u64 %0, t; }" : "=r"(a) : "l"(p));
    return a;
}
__device__ __forceinline__ void cp_async16(uint32_t dst, const void* src) {
    asm volatile(
        "{ .reg .u64 gp; cvta.to.global.u64 gp, %1;"
        " cp.async.cg.shared.global [%0], [gp], 16; }"
        :: "r"(dst), "l"(src) : "memory");
}
#define CP_COMMIT()  asm volatile("cp.async.commit_group;" ::: "memory")
#define CP_WAIT1()   asm volatile("cp.async.wait_group 1;" ::: "memory")
#define CP_WAIT0()   asm volatile("cp.async.wait_group 0;" ::: "memory")

__device__ __forceinline__ void ldsm4(uint32_t addr, uint32_t* r) {
    asm volatile("ldmatrix.sync.aligned.m8n8.x4.shared.b16 {%0,%1,%2,%3}, [%4];"
                 : "=r"(r[0]), "=r"(r[1]), "=r"(r[2]), "=r"(r[3]) : "r"(addr));
}
__device__ __forceinline__ void mma_f16(float* c, const uint32_t* a,
                                        uint32_t b0, uint32_t b1) {
    asm volatile(
        "mma.sync.aligned.m16n8k16.row.col.f32.f16.f16.f32 "
        "{%0,%1,%2,%3}, {%4,%5,%6,%7}, {%8,%9}, {%0,%1,%2,%3};"
        : "+f"(c[0]), "+f"(c[1]), "+f"(c[2]), "+f"(c[3])
        : "r"(a[0]), "r"(a[1]), "r"(a[2]), "r"(a[3]), "r"(b0), "r"(b1));
}
__device__ __forceinline__ float wsum(float v) {
#pragma unroll
    for (int o = 16; o > 0; o >>= 1) v += __shfl_xor_sync(0xffffffffu, v, o);
    return v;
}
// scale by A_SCALE and convert one float2 -> fp16x2 (normal range)
__device__ __forceinline__ uint32_t cvt2(float2 f) {
    __half2 h = __floats2half2_rn(f.x * A_SCALE, f.y * A_SCALE);
    return *(const uint32_t*)&h;
}

// ---------------------------------------------------------------------------
// Kernel A: hyperbolic transform -> tangent -> single fp16, K-major transposed.
// (unchanged, proven)
// ---------------------------------------------------------------------------
__global__ __launch_bounds__(256) void transform_kernel(
    const float* __restrict__ X,
    const float* __restrict__ W,
    const float* __restrict__ bias)
{
    __shared__ float2 sW2[DIN * 32];   // [k][t] = (W[k][t], W[k][t+32])

    const int tid = threadIdx.x;
    for (int i = tid; i < DIN * 32; i += 256) {
        const int k = i >> 5, t = i & 31;
        sW2[i] = make_float2(W[k * DOUT + t], W[k * DOUT + t + 32]);
    }
    __syncthreads();

    const int w    = tid >> 5;
    const int lane = tid & 31;
    const int row  = blockIdx.x * 8 + w;

    // hyp_bias = proj(expmap0(bias))
    float b1 = bias[lane], b2v = bias[lane + 32];
    float b2 = wsum(b1 * b1 + b2v * b2v);
    float bn = fmaxf(sqrtf(b2), MIN_NORM);
    float tb = tanhf(bn) / bn;
    float e1 = tb * b1, e2v = tb * b2v;
    float e2 = wsum(e1 * e1 + e2v * e2v);
    float en = fmaxf(sqrtf(e2), MIN_NORM);
    float sc = (en > MAXNORM) ? (MAXNORM / en) : 1.f;
    float h1 = e1 * sc, h2v = e2v * sc;
    float h2 = wsum(h1 * h1 + h2v * h2v);

    float xr[4];
#pragma unroll
    for (int j = 0; j < 4; ++j) xr[j] = X[(size_t)row * DIN + lane + 32 * j];
    float x2 = wsum(xr[0] * xr[0] + xr[1] * xr[1] + xr[2] * xr[2] + xr[3] * xr[3]);

    float ma = 0.f, mb = 0.f;
#pragma unroll
    for (int j = 0; j < 4; ++j) {
#pragma unroll
        for (int l = 0; l < 32; ++l) {
            const float xv = __shfl_sync(0xffffffffu, xr[j], l);
            const float2 wv = sW2[(j * 32 + l) * 32 + lane];
            ma = fmaf(xv, wv.x, ma);
            mb = fmaf(xv, wv.y, mb);
        }
    }

    float m2 = wsum(ma * ma + mb * mb);
    float xn = fmaxf(sqrtf(x2), MIN_NORM);
    float mn = fmaxf(sqrtf(m2), MIN_NORM);

    float artx = atanhf(fminf(xn, ART_CLAMP));
    float tf   = tanhf(mn / xn * artx) / mn;
    float r1 = tf * ma, r2v = tf * mb;
    if (m2 == 0.f) { r1 = 0.f; r2v = 0.f; }

    float r2 = wsum(r1 * r1 + r2v * r2v);
    float rh = wsum(r1 * h1 + r2v * h2v);
    float al  = 1.f + 2.f * rh + h2;
    float den = fmaxf(1.f + 2.f * rh + r2 * h2, MIN_NORM);
    float p1  = (al * r1  + (1.f - r2) * h1)  / den;
    float p2v = (al * r2v + (1.f - r2) * h2v) / den;

    float p2 = wsum(p1 * p1 + p2v * p2v);
    float pn = fmaxf(sqrtf(p2), MIN_NORM);
    if (pn > MAXNORM) {
        float s = MAXNORM / pn;
        p1 *= s; p2v *= s; pn = MAXNORM;
    }

    float lf = atanhf(fminf(pn, ART_CLAMP)) / pn;
    g_Bf[(size_t)lane * KDIM + row]        = __float2half(lf * p1);
    g_Bf[(size_t)(lane + 32) * KDIM + row] = __float2half(lf * p2v);
}

// ---------------------------------------------------------------------------
// Kernel B: out = relu(A @ T), both operands single fp16 (A scaled 2^14).
// 256 CTAs x 256 thr (M64), 2 independent CTAs/SM — barrier-decoupled latency
// hiding. 8 warps = 4 m-groups x 2 k-halves. 3-stage cp.async A+B.
// k-half partials reduced via smem at epilogue.
// ---------------------------------------------------------------------------
__global__ __launch_bounds__(256, 2) void gemm_kernel(
    const float* __restrict__ A,
    float* __restrict__ out)
{
    extern __shared__ __align__(128) char sm[];   // [stage][A(17408) | B(9216)]

    const int tid   = threadIdx.x;
    const int w     = tid >> 5;
    const int lane  = tid & 31;
    const int g     = lane >> 2;
    const int t4    = lane & 3;
    const int mg    = w >> 1;       // m-group 0..3
    const int khalf = w & 1;        // k32 half of each chunk
    const int m0    = blockIdx.x * MTILE;

    const uint32_t sb0 = smem_u32(sm);

    // cp.async mappings (fully coalesced; A: 4 chunks/thr, B: 2 chunks/thr)
    const int rA0 = tid >> 4, kcA = tid & 15;    // A rows rA0+16j (j<4), 16B chunk kcA
    const int rB0 = tid >> 3, kcB = tid & 7;     // B rows rB0+32j (j<2), 16B chunk kcB
    const float*  srcA0 = A + (size_t)(m0 + rA0) * KDIM + kcA * 4;
    const __half* srcB0 = g_Bf + (size_t)rB0 * KDIM + kcB * 8;
    const uint32_t dstA0 = (uint32_t)(rA0 * APITCH + kcA * 16);
    const uint32_t dstB0 = (uint32_t)(ATILE + rB0 * BPITCH + kcB * 16);

    // A LDS offsets (byte): rows mg*16+g (+8); khalf selects k32 (128B)
    const uint32_t aRow0 = (uint32_t)((mg * 16 + g) * APITCH + khalf * 128 + 8 * t4);
    const uint32_t aRow1 = aRow0 + 8 * APITCH;

    // ldmatrix lane offset within B tile (+ khalf selects k32 = 64B)
    const uint32_t lmOff = (uint32_t)(ATILE + (lane & 7) * BPITCH + (lane >> 3) * 16
                                      + khalf * 64);

    float acc[8][4];
#pragma unroll
    for (int i = 0; i < 8; ++i)
#pragma unroll
        for (int j = 0; j < 4; ++j) acc[i][j] = 0.f;

    // prologue: stages 0,1
#pragma unroll
    for (int s = 0; s < 2; ++s) {
        const int kb = s * TK;
        const uint32_t db = sb0 + (uint32_t)(s * STAGE);
#pragma unroll
        for (int j = 0; j < 4; ++j)
            cp_async16(db + dstA0 + (uint32_t)(j * 16 * APITCH),
                       srcA0 + (size_t)j * 16 * KDIM + kb);
#pragma unroll
        for (int j = 0; j < 2; ++j)
            cp_async16(db + dstB0 + (uint32_t)(j * 32 * BPITCH),
                       srcB0 + (size_t)j * 32 * KDIM + kb);
        CP_COMMIT();
    }

    uint32_t ahF[8];
    uint32_t bf[8][4];

    for (int i = 0; i < NCH; ++i) {
        const int s = i % BSTAGES;

        if (i < NCH - 1) { CP_WAIT1(); } else { CP_WAIT0(); }
        __syncthreads();

        // issue stage i+2 (slot consumed at chunk i-1; barrier above makes it safe)
        if (i + 2 < NCH) {
            const int kb = (i + 2) * TK;
            const uint32_t db = sb0 + (uint32_t)(((i + 2) % BSTAGES) * STAGE);
#pragma unroll
            for (int j = 0; j < 4; ++j)
                cp_async16(db + dstA0 + (uint32_t)(j * 16 * APITCH),
                           srcA0 + (size_t)j * 16 * KDIM + kb);
#pragma unroll
            for (int j = 0; j < 2; ++j)
                cp_async16(db + dstB0 + (uint32_t)(j * 32 * BPITCH),
                           srcB0 + (size_t)j * 32 * KDIM + kb);
            CP_COMMIT();
        }

        // build A fragments for this warp's k32: LDS float2 -> scale + cvt
        const char* stg = sm + (size_t)s * STAGE;
#pragma unroll
        for (int kf = 0; kf < 2; ++kf) {
            const uint32_t c = (uint32_t)(kf * 64);
            ahF[kf * 4 + 0] = cvt2(*(const float2*)(stg + aRow0 + c));        // (g,   k)
            ahF[kf * 4 + 1] = cvt2(*(const float2*)(stg + aRow1 + c));        // (g+8, k)
            ahF[kf * 4 + 2] = cvt2(*(const float2*)(stg + aRow0 + c + 32));   // (g,   k+8)
            ahF[kf * 4 + 3] = cvt2(*(const float2*)(stg + aRow1 + c + 32));   // (g+8, k+8)
        }

        const uint32_t bBase = sb0 + (uint32_t)(s * STAGE) + lmOff;

        // all ldsm first, then nt-major bursts (acc reuse distance 8)
#pragma unroll
        for (int nt = 0; nt < 8; ++nt)
            ldsm4(bBase + (uint32_t)(nt * 8 * BPITCH), bf[nt]);
#pragma unroll
        for (int nt = 0; nt < 8; ++nt) mma_f16(acc[nt], ahF,     bf[nt][0], bf[nt][1]);
#pragma unroll
        for (int nt = 0; nt < 8; ++nt) mma_f16(acc[nt], ahF + 4, bf[nt][2], bf[nt][3]);
    }

    // k-half reduction via smem (reuses pipeline buffers), then relu + store
    __syncthreads();
    float* red = (float*)sm;
    if (khalf == 1) {
        float* dst = red + (size_t)mg * 1024 + lane * 32;
#pragma unroll
        for (int nt = 0; nt < 8; ++nt)
#pragma unroll
            for (int j = 0; j < 4; ++j) dst[nt * 4 + j] = acc[nt][j];
    }
    __syncthreads();
    if (khalf == 0) {
        const float invS = 1.f / A_SCALE;
        const float* src = red + (size_t)mg * 1024 + lane * 32;
        const int rowTop = m0 + mg * 16 + g;
#pragma unroll
        for (int nt = 0; nt < 8; ++nt) {
            const int col = nt * 8 + t4 * 2;
            float2 v0 = make_float2(fmaxf((acc[nt][0] + src[nt * 4 + 0]) * invS, 0.f),
                                    fmaxf((acc[nt][1] + src[nt * 4 + 1]) * invS, 0.f));
            float2 v1 = make_float2(fmaxf((acc[nt][2] + src[nt * 4 + 2]) * invS, 0.f),
                                    fmaxf((acc[nt][3] + src[nt * 4 + 3]) * invS, 0.f));
            *(float2*)(out + (size_t)rowTop * DOUT + col)       = v0;
            *(float2*)(out + (size_t)(rowTop + 8) * DOUT + col) = v1;
        }
    }
}

// ---------------------------------------------------------------------------
extern "C" void kernel_launch(void* const* d_in, const int* in_sizes, int n_in,
                              void* d_out, int out_size)
{
    const float* adj  = (const float*)d_in[0];   // [16384, 16384]
    const float* x    = (const float*)d_in[1];   // [16384, 128]
    const float* w    = (const float*)d_in[2];   // [128, 64]
    const float* bias = (const float*)d_in[3];   // [64]
    float* out = (float*)d_out;                  // [16384, 64]

    cudaFuncSetAttribute(gemm_kernel, cudaFuncAttributeMaxDynamicSharedMemorySize, SMEM_BYTES);

    transform_kernel<<<N_ROWS / 8, 256>>>(x, w, bias);
    gemm_kernel<<<N_ROWS / MTILE, 256, SMEM_BYTES>>>(adj, out);
}